// round 15
// baseline (speedup 1.0000x reference)
#include <cuda_runtime.h>
#include <cuda.h>
#include <cuda_fp16.h>
#include <cstdint>
#include <math.h>

// CRU: B=2048, T=512, D=64, H=512, NT=8
// tcgen05 kind::f16 SS recurrence (same fp16 data as the 13.75ms mma.sync
// kernel -> same accuracy class), pipeline per step:
//   grid (16 m, 8 nt), 160 thr. Warp4: 3-stage TMA + MMA. Warps 0-3: TMEM
//   epilogue -> fused gates -> h_next (decay_{t+1} pre-applied).
//   A (ping-pong, fp16) = [ h (512) | inp_t (128) ] row-major [2048][640]
//   gW fp16 [1536][640], nt-tile rows interleaved c = jl*3+g (gate triples
//   adjacent -> D cols r,z,n adjacent in TMEM).
//   gWn fp16 [512][128]: W_ih n-gate rows (side GEMM splits gi_n/gh_n).
//   gF fp32 ping-pong: exact h for the z*h_prev blend + head GEMM.
// Hang-proofing: ALL mbarrier waits are bounded (wrong answer instead of
// container-killing hang). Arch-specific asm is guarded so the harness's
// generic compute_103 PTX pass compiles; the sm_103a cubin runs the real code.

#if defined(__CUDA_ARCH_SPECIFIC__) || defined(__CUDA_ARCH_FAMILY_SPECIFIC__) || \
    defined(__CUDA_ARCH_FEAT_SM103_ALL) || defined(__CUDA_ARCH_FEAT_SM101_ALL) || \
    defined(__CUDA_ARCH_FEAT_SM100_ALL)
#define CRU_ARCH_OK 1
#else
#define CRU_ARCH_OK 0
#endif

__device__ __half g_A0[2048 * 640];
__device__ __half g_A1[2048 * 640];
__device__ float  g_F0[2048 * 512];
__device__ float  g_F1[2048 * 512];
__device__ __half g_W [1536 * 640];
__device__ __half g_Wn[ 512 * 128];
__device__ float  g_dt[ 512 * 2048];

// stage = A(16K) + W(24K) + Wn(8K) = 48KB, x3 stages
#define STAGE_BYTES 49152
#define OFFB   16384
#define OFFB2  40960
#define SM_MAIN   (3 * STAGE_BYTES)          // 147456
#define OFF_FULL  (SM_MAIN)                  // 3 x 8B
#define OFF_FREE  (SM_MAIN + 24)             // 3 x 8B
#define OFF_DONE  (SM_MAIN + 48)
#define OFF_TMEM  (SM_MAIN + 56)
#define OFF_BIAS  (SM_MAIN + 64)             // 6 x 64 floats
#define SMEM_TOTAL (SM_MAIN + 64 + 1536)     // 149056

// idesc kind::f16 (f16 inputs, f32 accum): dtype F32(1<<4), atype=btype=0,
// N>>3 <<17, M>>4 <<24
#define IDESC0 ((1u<<4) | (24u<<17) | (8u<<24))   // N=192, M=128
#define IDESC1 ((1u<<4) | ( 8u<<17) | (8u<<24))   // N=64,  M=128

static constexpr uint64_t DESC_SW128 =
    (2ull << 61) | (1ull << 46) | (64ull << 32) | (1ull << 16);

__device__ __forceinline__ uint64_t mk_desc(uint32_t a) {
    return DESC_SW128 | ((uint64_t)(a >> 4) & 0x3FFF);
}
__device__ __forceinline__ uint32_t s2u(const void* p) {
    uint32_t a;
    asm("{ .reg .u64 t; cvta.to.shared.u64 t, %1; cvt.u32.u64 %0, t; }" : "=r"(a) : "l"(p));
    return a;
}
__device__ __forceinline__ uint32_t elect1() {
    uint32_t p;
    asm volatile("{ .reg .pred p; elect.sync _|p, 0xFFFFFFFF; selp.b32 %0,1,0,p; }" : "=r"(p));
    return p;
}
__device__ __forceinline__ void mb_init(uint32_t a) {
    asm volatile("mbarrier.init.shared.b64 [%0], 1;" :: "r"(a) : "memory");
}
__device__ __forceinline__ void mb_exp_tx(uint32_t a, uint32_t tx) {
    asm volatile("mbarrier.arrive.expect_tx.shared.b64 _, [%0], %1;" :: "r"(a), "r"(tx) : "memory");
}
// BOUNDED wait: on protocol bug we fall through (wrong answer, no hang).
__device__ __forceinline__ void mb_wait(uint32_t a, uint32_t ph) {
    for (int it = 0; it < (1 << 22); ++it) {
        uint32_t done;
        asm volatile("{ .reg .pred P; "
            "mbarrier.try_wait.parity.acquire.cta.shared::cta.b64 P, [%1], %2, 0x989680; "
            "selp.b32 %0, 1, 0, P; }"
            : "=r"(done) : "r"(a), "r"(ph) : "memory");
        if (done) return;
    }
}

#if CRU_ARCH_OK
#define TMA2D(sa, tmp, cx, cy, mb) \
    asm volatile("cp.async.bulk.tensor.2d.shared::cta.global.tile.mbarrier::complete_tx::bytes " \
                 "[%0], [%1, {%2, %3}], [%4];" \
                 :: "r"(sa), "l"(tmp), "r"(cx), "r"(cy), "r"(mb) : "memory")

__device__ __forceinline__ void mma_f16(uint32_t d, uint64_t da, uint64_t db,
                                        uint32_t idesc, bool en) {
    uint32_t e = en ? 1u : 0u;
    asm volatile("{\n\t.reg .pred p;\n\tsetp.ne.u32 p, %5, 0;\n\t"
        "tcgen05.mma.cta_group::1.kind::f16 [%0], %1, %2, %3, {%4,%4,%4,%4}, p;\n\t}"
        :: "r"(d), "l"(da), "l"(db), "r"(idesc), "r"(0u), "r"(e) : "memory");
}
#define TCALLOC(sm, n)  asm volatile("tcgen05.alloc.cta_group::1.sync.aligned.shared::cta.b32 [%0], %1;" :: "r"(sm), "r"(n) : "memory")
#define TCRELINQ()      asm volatile("tcgen05.relinquish_alloc_permit.cta_group::1.sync.aligned;")
#define TCDEALLOC(t, n) asm volatile("tcgen05.dealloc.cta_group::1.sync.aligned.b32 %0, %1;" :: "r"(t), "r"(n))
#define TCCOMMIT(mb)    asm volatile("tcgen05.commit.cta_group::1.mbarrier::arrive::one.shared::cluster.b64 [%0];" :: "r"(mb) : "memory")
#define TCFENCE_AFTER() asm volatile("tcgen05.fence::after_thread_sync;" ::: "memory")
#define TCWAIT_LD()     asm volatile("tcgen05.wait::ld.sync.aligned;" ::: "memory")

#define LDTM32(r, addr) \
    asm volatile("tcgen05.ld.sync.aligned.32x32b.x32.b32 " \
        "{%0,%1,%2,%3,%4,%5,%6,%7,%8,%9,%10,%11,%12,%13,%14,%15," \
        "%16,%17,%18,%19,%20,%21,%22,%23,%24,%25,%26,%27,%28,%29,%30,%31}, [%32];" \
        : "=r"((r)[0]),"=r"((r)[1]),"=r"((r)[2]),"=r"((r)[3]),"=r"((r)[4]),"=r"((r)[5]), \
          "=r"((r)[6]),"=r"((r)[7]),"=r"((r)[8]),"=r"((r)[9]),"=r"((r)[10]),"=r"((r)[11]), \
          "=r"((r)[12]),"=r"((r)[13]),"=r"((r)[14]),"=r"((r)[15]),"=r"((r)[16]),"=r"((r)[17]), \
          "=r"((r)[18]),"=r"((r)[19]),"=r"((r)[20]),"=r"((r)[21]),"=r"((r)[22]),"=r"((r)[23]), \
          "=r"((r)[24]),"=r"((r)[25]),"=r"((r)[26]),"=r"((r)[27]),"=r"((r)[28]),"=r"((r)[29]), \
          "=r"((r)[30]),"=r"((r)[31]) : "r"(addr))
#endif  // CRU_ARCH_OK

__device__ __forceinline__ float sigmoidf_(float x) { return 1.0f / (1.0f + __expf(-x)); }
__device__ __forceinline__ float tanhfast(float x) {
    float y; asm("tanh.approx.f32 %0, %1;" : "=f"(y) : "f"(x)); return y;
}

// ---------------- prep kernels ----------------
// W rows interleaved within nt tile: row nt*192 + jl*3 + g  <-  W[g*512+nt*64+jl]
__global__ void prep_w_kernel(const float* __restrict__ W_ih, const float* __restrict__ W_hh) {
    int idx = blockIdx.x * 256 + threadIdx.x;          // 1536*640
    if (idx >= 1536 * 640) return;
    int r = idx / 640, k = idx - r * 640;
    int nt = r / 192, rem = r - nt * 192;
    int jl = rem / 3, g = rem - jl * 3;
    int row = g * 512 + nt * 64 + jl;
    float w = (k < 512) ? W_hh[(size_t)row * 512 + k] : W_ih[(size_t)row * 128 + (k - 512)];
    g_W[idx] = __float2half_rn(w);
}
__global__ void prep_wn_kernel(const float* __restrict__ W_ih) {
    int idx = blockIdx.x * 256 + threadIdx.x;          // 512*128
    int j = idx >> 7, k = idx & 127;
    g_Wn[idx] = __float2half_rn(W_ih[(size_t)(1024 + j) * 128 + k]);
}
__global__ void prep_dt_kernel(const float* __restrict__ ts) {
    int t = blockIdx.x;
    for (int b = threadIdx.x; b < 2048; b += 256) {
        float d = 0.0f;
        if (t > 0) d = ts[(size_t)b * 512 + t] - ts[(size_t)b * 512 + t - 1];
        g_dt[t * 2048 + b] = d;
    }
}
__global__ void prep_a0_kernel(const float* __restrict__ vals, const float* __restrict__ maskp) {
    int b = blockIdx.x;
    for (int i = threadIdx.x; i < 640; i += 256) {
        float v = 0.0f;
        if (i >= 512 && i < 576)      v = vals [(size_t)b * 32768 + (i - 512)];
        else if (i >= 576)            v = maskp[(size_t)b * 32768 + (i - 576)];
        g_A0[(size_t)b * 640 + i] = __float2half_rn(v);
    }
    for (int i = threadIdx.x; i < 512; i += 256)
        g_F0[(size_t)b * 512 + i] = 0.0f;
}

// ---------------- step kernel ----------------
__global__ void __launch_bounds__(160, 1) cru_step_kernel(
    const __grid_constant__ CUtensorMap tmA,
    const __grid_constant__ CUtensorMap tmW,
    const __grid_constant__ CUtensorMap tmWn,
    const float* __restrict__ vals, const float* __restrict__ maskp,
    const float* __restrict__ b_ih, const float* __restrict__ b_hh,
    const float* __restrict__ Wd,  const float* __restrict__ bdp,
    const float* __restrict__ Fcur, float* __restrict__ Fnext,
    __half* __restrict__ Anext, int t)
{
#if CRU_ARCH_OK
    extern __shared__ __align__(1024) char smem[];
    const uint32_t sb = s2u(smem);
    const int tid = threadIdx.x, wid = tid >> 5, lane = tid & 31;
    const int m = blockIdx.x, nt = blockIdx.y;
    float* sB = (float*)(smem + OFF_BIAS);

    if (wid == 4) { TCALLOC(sb + OFF_TMEM, 256); TCRELINQ(); }
    if (tid == 0) {
        for (int s = 0; s < 3; ++s) { mb_init(sb + OFF_FULL + s * 8); mb_init(sb + OFF_FREE + s * 8); }
        mb_init(sb + OFF_DONE);
    }
    __syncthreads();
    uint32_t tmem;
    asm volatile("ld.shared.b32 %0, [%1];" : "=r"(tmem) : "r"(sb + OFF_TMEM));

    if (wid == 4) {
        if (elect1()) {
            // prologue: stages 0..2 (chunks 0..2, all k<512 -> no Wn)
            for (int c = 0; c < 3; ++c) {
                int s = c;
                mb_exp_tx(sb + OFF_FULL + s * 8, 40960u);
                TMA2D(sb + s * STAGE_BYTES,        &tmA, c * 64, m * 128,  sb + OFF_FULL + s * 8);
                TMA2D(sb + s * STAGE_BYTES + OFFB, &tmW, c * 64, nt * 192, sb + OFF_FULL + s * 8);
            }
            for (int c = 0; c < 10; ++c) {
                int s = c % 3; uint32_t ph = (uint32_t)(c / 3) & 1u;
                mb_wait(sb + OFF_FULL + s * 8, ph);
                uint64_t da = mk_desc(sb + s * STAGE_BYTES);
                uint64_t db = mk_desc(sb + s * STAGE_BYTES + OFFB);
#pragma unroll
                for (int u = 0; u < 4; ++u)   // K=16 f16 per dispatch, +32B per step
                    mma_f16(tmem, da + 2 * u, db + 2 * u, IDESC0, (c > 0) || (u > 0));
                if (c >= 8) {
                    uint64_t db2 = mk_desc(sb + s * STAGE_BYTES + OFFB2);
#pragma unroll
                    for (int u = 0; u < 4; ++u)
                        mma_f16(tmem + 192, da + 2 * u, db2 + 2 * u, IDESC1, (c > 8) || (u > 0));
                }
                TCCOMMIT(sb + OFF_FREE + s * 8);
                if (c + 3 < 10) {
                    mb_wait(sb + OFF_FREE + s * 8, ph);
                    int k = (c + 3) * 64;                   // halves
                    uint32_t tx = (k >= 512) ? 49152u : 40960u;
                    mb_exp_tx(sb + OFF_FULL + s * 8, tx);
                    TMA2D(sb + s * STAGE_BYTES,        &tmA, k, m * 128,  sb + OFF_FULL + s * 8);
                    TMA2D(sb + s * STAGE_BYTES + OFFB, &tmW, k, nt * 192, sb + OFF_FULL + s * 8);
                    if (k >= 512)
                        TMA2D(sb + s * STAGE_BYTES + OFFB2, &tmWn, k - 512, nt * 64, sb + OFF_FULL + s * 8);
                }
            }
            TCCOMMIT(sb + OFF_DONE);
        }
    } else {
        // ---- epilogue warps 0..3 ----
        if (tid < 64) {
            int j = nt * 64 + tid;
            sB[tid]        = b_ih[j]        + b_hh[j];
            sB[64 + tid]   = b_ih[512 + j]  + b_hh[512 + j];
            sB[128 + tid]  = b_ih[1024 + j];
            sB[192 + tid]  = b_hh[1024 + j];
            sB[256 + tid]  = Wd[j];
            sB[320 + tid]  = bdp[j];
        }
        asm volatile("bar.sync 1, 128;" ::: "memory");
        mb_wait(sb + OFF_DONE, 0);
        TCFENCE_AFTER();

        const int b = m * 128 + wid * 32 + lane;
        const uint32_t tw = tmem + ((uint32_t)wid << 21);
        float dtn = 0.0f;
        if (t < 511) dtn = g_dt[(size_t)(t + 1) * 2048 + b];
        const float* fr = Fcur + (size_t)b * 512 + nt * 64;
        float* fw = Fnext + (size_t)b * 512 + nt * 64;
        __half* aw = Anext + (size_t)b * 640 + nt * 64;

#pragma unroll
        for (int q = 0; q < 2; ++q) {
            uint32_t a[96], g1[32];
            LDTM32(a,      tw + q * 96);
            LDTM32(a + 32, tw + q * 96 + 32);
            LDTM32(a + 64, tw + q * 96 + 64);
            LDTM32(g1,     tw + 192 + q * 32);
            TCWAIT_LD();
            float hprev[32];
            const float4* hp4 = (const float4*)(fr + q * 32);
#pragma unroll
            for (int i = 0; i < 8; ++i) {
                float4 v = hp4[i];
                hprev[4 * i] = v.x; hprev[4 * i + 1] = v.y;
                hprev[4 * i + 2] = v.z; hprev[4 * i + 3] = v.w;
            }
            float hout[32];
#pragma unroll
            for (int u = 0; u < 32; ++u) {
                int j = q * 32 + u;
                float sr  = __uint_as_float(a[3 * u]);
                float szv = __uint_as_float(a[3 * u + 1]);
                float sn  = __uint_as_float(a[3 * u + 2]);
                float gin = __uint_as_float(g1[u]);
                float r = sigmoidf_(sr + sB[j]);
                float z = sigmoidf_(szv + sB[64 + j]);
                float n = tanhfast(gin + sB[128 + j] + r * ((sn - gin) + sB[192 + j]));
                float h = fmaf(-z, n, n) + z * hprev[u];
                if (t < 511)  // exp(-softplus(x)) == sigmoid(-x)
                    h *= sigmoidf_(-(dtn * sB[256 + j] + sB[320 + j]));
                hout[u] = h;
            }
            float4* fw4 = (float4*)(fw + q * 32);
#pragma unroll
            for (int i = 0; i < 8; ++i)
                fw4[i] = make_float4(hout[4 * i], hout[4 * i + 1], hout[4 * i + 2], hout[4 * i + 3]);
            __half2* aw2 = (__half2*)(aw + q * 32);
#pragma unroll
            for (int i = 0; i < 16; ++i)
                aw2[i] = __floats2half2_rn(hout[2 * i], hout[2 * i + 1]);
        }

        // ---- nt==0: stage inp_{t+1} (fp16) into A_next ----
        if (nt == 0 && t < 511) {
#pragma unroll
            for (int i = 0; i < 32; i++) {
                int op = tid + i * 128;          // 4096 float4-load ops
                int bl = op >> 5, seg = op & 31;
                int bb = m * 128 + bl;
                float4 v;
                if (seg < 16)
                    v = ((const float4*)(vals  + (size_t)bb * 32768 + (size_t)(t + 1) * 64))[seg];
                else
                    v = ((const float4*)(maskp + (size_t)bb * 32768 + (size_t)(t + 1) * 64))[seg - 16];
                __half2* dst = (__half2*)(Anext + (size_t)bb * 640 + 512 + seg * 4);
                dst[0] = __floats2half2_rn(v.x, v.y);
                dst[1] = __floats2half2_rn(v.z, v.w);
            }
        }
    }
    __syncthreads();
    if (wid == 4) TCDEALLOC(tmem, 256);
#endif  // CRU_ARCH_OK
}

// ---------------- head ----------------
__global__ void cru_head_kernel(const float* __restrict__ W_head,
                                const float* __restrict__ b_head,
                                float* __restrict__ out)
{
    __shared__ float sW[8 * 512];
    int tid = threadIdx.x;
    for (int i = tid; i < 4096; i += 128) sW[i] = W_head[i];
    __syncthreads();
    int b = blockIdx.x * 128 + tid;
    const float4* h4 = (const float4*)(g_F0 + (size_t)b * 512);  // t=511 writes F0
    float acc[8];
#pragma unroll
    for (int n = 0; n < 8; n++) acc[n] = 0.f;
    for (int j4 = 0; j4 < 128; ++j4) {
        float4 v = h4[j4];
#pragma unroll
        for (int n = 0; n < 8; n++) {
            acc[n] = fmaf(v.x, sW[n * 512 + 4 * j4],     acc[n]);
            acc[n] = fmaf(v.y, sW[n * 512 + 4 * j4 + 1], acc[n]);
            acc[n] = fmaf(v.z, sW[n * 512 + 4 * j4 + 2], acc[n]);
            acc[n] = fmaf(v.w, sW[n * 512 + 4 * j4 + 3], acc[n]);
        }
    }
#pragma unroll
    for (int n = 0; n < 8; n++) out[b * 8 + n] = acc[n] + b_head[n];
}

// ---------------- host ----------------
typedef CUresult (*EncFn)(CUtensorMap*, CUtensorMapDataType, cuuint32_t, void*,
                          const cuuint64_t*, const cuuint64_t*, const cuuint32_t*,
                          const cuuint32_t*, CUtensorMapInterleave, CUtensorMapSwizzle,
                          CUtensorMapL2promotion, CUtensorMapFloatOOBfill);

static void make_tm2d_f16(EncFn enc, CUtensorMap* tm, void* ptr,
                          uint64_t d0, uint64_t d1, uint32_t b0, uint32_t b1) {
    cuuint64_t dims[2] = {d0, d1};
    cuuint64_t strides[1] = {d0 * 2};
    cuuint32_t box[2] = {b0, b1};
    cuuint32_t es[2] = {1, 1};
    enc(tm, CU_TENSOR_MAP_DATA_TYPE_FLOAT16, 2, ptr, dims, strides, box, es,
        CU_TENSOR_MAP_INTERLEAVE_NONE, CU_TENSOR_MAP_SWIZZLE_128B,
        CU_TENSOR_MAP_L2_PROMOTION_L2_128B, CU_TENSOR_MAP_FLOAT_OOB_FILL_NONE);
}

extern "C" void kernel_launch(void* const* d_in, const int* in_sizes, int n_in,
                              void* d_out, int out_size)
{
    const float* vals   = (const float*)d_in[0];
    const float* maskp  = (const float*)d_in[1];
    const float* ts     = (const float*)d_in[2];
    const float* W_ih   = (const float*)d_in[3];
    const float* W_hh   = (const float*)d_in[4];
    const float* b_ih   = (const float*)d_in[5];
    const float* b_hh   = (const float*)d_in[6];
    const float* W_dec  = (const float*)d_in[7];
    const float* b_dec  = (const float*)d_in[8];
    const float* W_head = (const float*)d_in[9];
    const float* b_head = (const float*)d_in[10];
    float* out = (float*)d_out;

    EncFn enc = nullptr;
    cudaDriverEntryPointQueryResult qr;
    cudaGetDriverEntryPointByVersion("cuTensorMapEncodeTiled", (void**)&enc, 12000,
                                     cudaEnableDefault, &qr);

    void *pA0, *pA1, *pW, *pWn, *pF0, *pF1;
    cudaGetSymbolAddress(&pA0, g_A0);
    cudaGetSymbolAddress(&pA1, g_A1);
    cudaGetSymbolAddress(&pW,  g_W);
    cudaGetSymbolAddress(&pWn, g_Wn);
    cudaGetSymbolAddress(&pF0, g_F0);
    cudaGetSymbolAddress(&pF1, g_F1);

    CUtensorMap tmA0, tmA1, tmW, tmWn;
    make_tm2d_f16(enc, &tmA0, pA0, 640, 2048, 64, 128);
    make_tm2d_f16(enc, &tmA1, pA1, 640, 2048, 64, 128);
    make_tm2d_f16(enc, &tmW,  pW,  640, 1536, 64, 192);
    make_tm2d_f16(enc, &tmWn, pWn, 128, 512,  64, 64);

    cudaFuncSetAttribute(cru_step_kernel,
                         cudaFuncAttributeMaxDynamicSharedMemorySize, SMEM_TOTAL);

    prep_w_kernel<<<3840, 256>>>(W_ih, W_hh);
    prep_wn_kernel<<<256, 256>>>(W_ih);
    prep_dt_kernel<<<512, 256>>>(ts);
    prep_a0_kernel<<<2048, 256>>>(vals, maskp);

    dim3 grid(16, 8);
    for (int t = 0; t < 512; ++t) {
        const float* Fcur = (t & 1) ? (const float*)pF1 : (const float*)pF0;
        float*       Fnxt = (t & 1) ? (float*)pF0 : (float*)pF1;
        __half*      Anxt = (t & 1) ? (__half*)pA0 : (__half*)pA1;
        if (t & 1)
            cru_step_kernel<<<grid, 160, SMEM_TOTAL>>>(tmA1, tmW, tmWn, vals, maskp,
                b_ih, b_hh, W_dec, b_dec, Fcur, Fnxt, Anxt, t);
        else
            cru_step_kernel<<<grid, 160, SMEM_TOTAL>>>(tmA0, tmW, tmWn, vals, maskp,
                b_ih, b_hh, W_dec, b_dec, Fcur, Fnxt, Anxt, t);
    }

    cru_head_kernel<<<16, 128>>>(W_head, b_head, out);
}

// round 16
// speedup vs baseline: 1.0559x; 1.0559x over previous
#include <cuda_runtime.h>
#include <cuda.h>
#include <cuda_fp16.h>
#include <cstdint>
#include <math.h>

// CRU: B=2048, T=512, D=64, H=512, NT=8
// tcgen05 kind::f16 SS recurrence, v2:
//   - 4-stage TMA pipeline (192KB smem) for deeper latency hiding
//   - epilogue global work (dt, inp_{t+1} staging) moved BEFORE the DONE wait
//   - all prep fused into ONE kernel so ncu (-s 5) captures the step kernel
// Per step: grid (16 m, 8 nt), 160 thr. Warp4 = TMA+MMA producer; warps 0-3 =
// TMEM epilogue -> fused gates -> h_next (decay_{t+1} pre-applied).
//   A (ping-pong, fp16) = [ h (512) | inp_t (128) ] row-major [2048][640]
//   gW fp16 [1536][640], nt-tile rows interleaved c = jl*3+g
//   gWn fp16 [512][128]: W_ih n-gate rows (side GEMM splits gi_n/gh_n)
//   gF fp32 ping-pong: exact h for z*h_prev blend + head GEMM
// All mbarrier waits bounded (bug -> wrong answer, never a hang). Arch-specific
// asm guarded for the harness's generic compute_103 PTX pass.

#if defined(__CUDA_ARCH_SPECIFIC__) || defined(__CUDA_ARCH_FAMILY_SPECIFIC__) || \
    defined(__CUDA_ARCH_FEAT_SM103_ALL) || defined(__CUDA_ARCH_FEAT_SM101_ALL) || \
    defined(__CUDA_ARCH_FEAT_SM100_ALL)
#define CRU_ARCH_OK 1
#else
#define CRU_ARCH_OK 0
#endif

__device__ __half g_A0[2048 * 640];
__device__ __half g_A1[2048 * 640];
__device__ float  g_F0[2048 * 512];
__device__ float  g_F1[2048 * 512];
__device__ __half g_W [1536 * 640];
__device__ __half g_Wn[ 512 * 128];
__device__ float  g_dt[ 512 * 2048];

// stage = A(16K) + W(24K) + Wn(8K) = 48KB, x4 stages
#define STAGE_BYTES 49152
#define OFFB   16384
#define OFFB2  40960
#define SM_MAIN   (4 * STAGE_BYTES)          // 196608
#define OFF_FULL  (SM_MAIN)                  // 4 x 8B
#define OFF_FREE  (SM_MAIN + 32)             // 4 x 8B
#define OFF_DONE  (SM_MAIN + 64)
#define OFF_TMEM  (SM_MAIN + 72)
#define OFF_BIAS  (SM_MAIN + 128)            // 6 x 64 floats
#define SMEM_TOTAL (SM_MAIN + 128 + 1536)    // 198272

// idesc kind::f16 (f16 in, f32 accum): dtype F32(1<<4), atype=btype=0
#define IDESC0 ((1u<<4) | (24u<<17) | (8u<<24))   // N=192, M=128
#define IDESC1 ((1u<<4) | ( 8u<<17) | (8u<<24))   // N=64,  M=128

static constexpr uint64_t DESC_SW128 =
    (2ull << 61) | (1ull << 46) | (64ull << 32) | (1ull << 16);

__device__ __forceinline__ uint64_t mk_desc(uint32_t a) {
    return DESC_SW128 | ((uint64_t)(a >> 4) & 0x3FFF);
}
__device__ __forceinline__ uint32_t s2u(const void* p) {
    uint32_t a;
    asm("{ .reg .u64 t; cvta.to.shared.u64 t, %1; cvt.u32.u64 %0, t; }" : "=r"(a) : "l"(p));
    return a;
}
__device__ __forceinline__ uint32_t elect1() {
    uint32_t p;
    asm volatile("{ .reg .pred p; elect.sync _|p, 0xFFFFFFFF; selp.b32 %0,1,0,p; }" : "=r"(p));
    return p;
}
__device__ __forceinline__ void mb_init(uint32_t a) {
    asm volatile("mbarrier.init.shared.b64 [%0], 1;" :: "r"(a) : "memory");
}
__device__ __forceinline__ void mb_exp_tx(uint32_t a, uint32_t tx) {
    asm volatile("mbarrier.arrive.expect_tx.shared.b64 _, [%0], %1;" :: "r"(a), "r"(tx) : "memory");
}
// BOUNDED wait: protocol bug -> wrong answer, never a container-killing hang.
__device__ __forceinline__ void mb_wait(uint32_t a, uint32_t ph) {
    for (int it = 0; it < (1 << 22); ++it) {
        uint32_t done;
        asm volatile("{ .reg .pred P; "
            "mbarrier.try_wait.parity.acquire.cta.shared::cta.b64 P, [%1], %2, 0x989680; "
            "selp.b32 %0, 1, 0, P; }"
            : "=r"(done) : "r"(a), "r"(ph) : "memory");
        if (done) return;
    }
}

#if CRU_ARCH_OK
#define TMA2D(sa, tmp, cx, cy, mb) \
    asm volatile("cp.async.bulk.tensor.2d.shared::cta.global.tile.mbarrier::complete_tx::bytes " \
                 "[%0], [%1, {%2, %3}], [%4];" \
                 :: "r"(sa), "l"(tmp), "r"(cx), "r"(cy), "r"(mb) : "memory")

__device__ __forceinline__ void mma_f16(uint32_t d, uint64_t da, uint64_t db,
                                        uint32_t idesc, bool en) {
    uint32_t e = en ? 1u : 0u;
    asm volatile("{\n\t.reg .pred p;\n\tsetp.ne.u32 p, %5, 0;\n\t"
        "tcgen05.mma.cta_group::1.kind::f16 [%0], %1, %2, %3, {%4,%4,%4,%4}, p;\n\t}"
        :: "r"(d), "l"(da), "l"(db), "r"(idesc), "r"(0u), "r"(e) : "memory");
}
#define TCALLOC(sm, n)  asm volatile("tcgen05.alloc.cta_group::1.sync.aligned.shared::cta.b32 [%0], %1;" :: "r"(sm), "r"(n) : "memory")
#define TCRELINQ()      asm volatile("tcgen05.relinquish_alloc_permit.cta_group::1.sync.aligned;")
#define TCDEALLOC(t, n) asm volatile("tcgen05.dealloc.cta_group::1.sync.aligned.b32 %0, %1;" :: "r"(t), "r"(n))
#define TCCOMMIT(mb)    asm volatile("tcgen05.commit.cta_group::1.mbarrier::arrive::one.shared::cluster.b64 [%0];" :: "r"(mb) : "memory")
#define TCFENCE_AFTER() asm volatile("tcgen05.fence::after_thread_sync;" ::: "memory")
#define TCWAIT_LD()     asm volatile("tcgen05.wait::ld.sync.aligned;" ::: "memory")

#define LDTM32(r, addr) \
    asm volatile("tcgen05.ld.sync.aligned.32x32b.x32.b32 " \
        "{%0,%1,%2,%3,%4,%5,%6,%7,%8,%9,%10,%11,%12,%13,%14,%15," \
        "%16,%17,%18,%19,%20,%21,%22,%23,%24,%25,%26,%27,%28,%29,%30,%31}, [%32];" \
        : "=r"((r)[0]),"=r"((r)[1]),"=r"((r)[2]),"=r"((r)[3]),"=r"((r)[4]),"=r"((r)[5]), \
          "=r"((r)[6]),"=r"((r)[7]),"=r"((r)[8]),"=r"((r)[9]),"=r"((r)[10]),"=r"((r)[11]), \
          "=r"((r)[12]),"=r"((r)[13]),"=r"((r)[14]),"=r"((r)[15]),"=r"((r)[16]),"=r"((r)[17]), \
          "=r"((r)[18]),"=r"((r)[19]),"=r"((r)[20]),"=r"((r)[21]),"=r"((r)[22]),"=r"((r)[23]), \
          "=r"((r)[24]),"=r"((r)[25]),"=r"((r)[26]),"=r"((r)[27]),"=r"((r)[28]),"=r"((r)[29]), \
          "=r"((r)[30]),"=r"((r)[31]) : "r"(addr))
#endif  // CRU_ARCH_OK

__device__ __forceinline__ float sigmoidf_(float x) { return 1.0f / (1.0f + __expf(-x)); }
__device__ __forceinline__ float tanhfast(float x) {
    float y; asm("tanh.approx.f32 %0, %1;" : "=f"(y) : "f"(x)); return y;
}

// ---------------- fused prep kernel (ONE launch) ----------------
// blocks [0,3840): W   [3840,4096): Wn   [4096,4608): dt   [4608,6656): A0/F0
__global__ void prep_all_kernel(const float* __restrict__ vals,
                                const float* __restrict__ maskp,
                                const float* __restrict__ ts,
                                const float* __restrict__ W_ih,
                                const float* __restrict__ W_hh)
{
    int blk = blockIdx.x, tid = threadIdx.x;
    if (blk < 3840) {
        int idx = blk * 256 + tid;                   // < 983040
        if (idx < 1536 * 640) {
            int r = idx / 640, k = idx - r * 640;
            int nt = r / 192, rem = r - nt * 192;
            int jl = rem / 3, g = rem - jl * 3;
            int row = g * 512 + nt * 64 + jl;
            float w = (k < 512) ? W_hh[(size_t)row * 512 + k]
                                : W_ih[(size_t)row * 128 + (k - 512)];
            g_W[idx] = __float2half_rn(w);
        }
    } else if (blk < 4096) {
        int idx = (blk - 3840) * 256 + tid;          // 512*128
        int j = idx >> 7, k = idx & 127;
        g_Wn[idx] = __float2half_rn(W_ih[(size_t)(1024 + j) * 128 + k]);
    } else if (blk < 4608) {
        int t = blk - 4096;
        for (int b = tid; b < 2048; b += 256) {
            float d = 0.0f;
            if (t > 0) d = ts[(size_t)b * 512 + t] - ts[(size_t)b * 512 + t - 1];
            g_dt[t * 2048 + b] = d;
        }
    } else {
        int b = blk - 4608;
        for (int i = tid; i < 640; i += 256) {
            float v = 0.0f;
            if (i >= 512 && i < 576)      v = vals [(size_t)b * 32768 + (i - 512)];
            else if (i >= 576)            v = maskp[(size_t)b * 32768 + (i - 576)];
            g_A0[(size_t)b * 640 + i] = __float2half_rn(v);
        }
        for (int i = tid; i < 512; i += 256)
            g_F0[(size_t)b * 512 + i] = 0.0f;
    }
}

// ---------------- step kernel ----------------
__global__ void __launch_bounds__(160, 1) cru_step_kernel(
    const __grid_constant__ CUtensorMap tmA,
    const __grid_constant__ CUtensorMap tmW,
    const __grid_constant__ CUtensorMap tmWn,
    const float* __restrict__ vals, const float* __restrict__ maskp,
    const float* __restrict__ b_ih, const float* __restrict__ b_hh,
    const float* __restrict__ Wd,  const float* __restrict__ bdp,
    const float* __restrict__ Fcur, float* __restrict__ Fnext,
    __half* __restrict__ Anext, int t)
{
#if CRU_ARCH_OK
    extern __shared__ __align__(1024) char smem[];
    const uint32_t sb = s2u(smem);
    const int tid = threadIdx.x, wid = tid >> 5, lane = tid & 31;
    const int m = blockIdx.x, nt = blockIdx.y;
    float* sB = (float*)(smem + OFF_BIAS);

    if (wid == 4) { TCALLOC(sb + OFF_TMEM, 256); TCRELINQ(); }
    if (tid == 0) {
        for (int s = 0; s < 4; ++s) { mb_init(sb + OFF_FULL + s * 8); mb_init(sb + OFF_FREE + s * 8); }
        mb_init(sb + OFF_DONE);
    }
    __syncthreads();
    uint32_t tmem;
    asm volatile("ld.shared.b32 %0, [%1];" : "=r"(tmem) : "r"(sb + OFF_TMEM));

    if (wid == 4) {
        if (elect1()) {
            // prologue: fill stages 0..3 (chunks 0..3, all k<512 -> no Wn)
            for (int c = 0; c < 4; ++c) {
                int s = c;
                mb_exp_tx(sb + OFF_FULL + s * 8, 40960u);
                TMA2D(sb + s * STAGE_BYTES,        &tmA, c * 64, m * 128,  sb + OFF_FULL + s * 8);
                TMA2D(sb + s * STAGE_BYTES + OFFB, &tmW, c * 64, nt * 192, sb + OFF_FULL + s * 8);
            }
            for (int c = 0; c < 10; ++c) {
                int s = c & 3; uint32_t ph = (uint32_t)(c >> 2) & 1u;
                mb_wait(sb + OFF_FULL + s * 8, ph);
                uint64_t da = mk_desc(sb + s * STAGE_BYTES);
                uint64_t db = mk_desc(sb + s * STAGE_BYTES + OFFB);
#pragma unroll
                for (int u = 0; u < 4; ++u)   // K=16 f16 per dispatch, +32B per step
                    mma_f16(tmem, da + 2 * u, db + 2 * u, IDESC0, (c > 0) || (u > 0));
                if (c >= 8) {
                    uint64_t db2 = mk_desc(sb + s * STAGE_BYTES + OFFB2);
#pragma unroll
                    for (int u = 0; u < 4; ++u)
                        mma_f16(tmem + 192, da + 2 * u, db2 + 2 * u, IDESC1, (c > 8) || (u > 0));
                }
                TCCOMMIT(sb + OFF_FREE + s * 8);
                if (c + 4 < 10) {
                    mb_wait(sb + OFF_FREE + s * 8, ph);
                    int k = (c + 4) * 64;                   // halves
                    uint32_t tx = (k >= 512) ? 49152u : 40960u;
                    mb_exp_tx(sb + OFF_FULL + s * 8, tx);
                    TMA2D(sb + s * STAGE_BYTES,        &tmA, k, m * 128,  sb + OFF_FULL + s * 8);
                    TMA2D(sb + s * STAGE_BYTES + OFFB, &tmW, k, nt * 192, sb + OFF_FULL + s * 8);
                    if (k >= 512)
                        TMA2D(sb + s * STAGE_BYTES + OFFB2, &tmWn, k - 512, nt * 64, sb + OFF_FULL + s * 8);
                }
            }
            TCCOMMIT(sb + OFF_DONE);
        }
    } else {
        // ---- epilogue warps 0..3: do ALL independent work BEFORE the wait ----
        if (tid < 64) {
            int j = nt * 64 + tid;
            sB[tid]        = b_ih[j]        + b_hh[j];
            sB[64 + tid]   = b_ih[512 + j]  + b_hh[512 + j];
            sB[128 + tid]  = b_ih[1024 + j];
            sB[192 + tid]  = b_hh[1024 + j];
            sB[256 + tid]  = Wd[j];
            sB[320 + tid]  = bdp[j];
        }
        const int b = m * 128 + wid * 32 + lane;
        float dtn = 0.0f;
        if (t < 511) dtn = g_dt[(size_t)(t + 1) * 2048 + b];

        // stage inp_{t+1} into A_next now (independent of this step's MMA)
        if (nt == 0 && t < 511) {
#pragma unroll
            for (int i = 0; i < 32; i++) {
                int op = tid + i * 128;          // 4096 float4-load ops
                int bl = op >> 5, seg = op & 31;
                int bb = m * 128 + bl;
                float4 v;
                if (seg < 16)
                    v = ((const float4*)(vals  + (size_t)bb * 32768 + (size_t)(t + 1) * 64))[seg];
                else
                    v = ((const float4*)(maskp + (size_t)bb * 32768 + (size_t)(t + 1) * 64))[seg - 16];
                __half2* dst = (__half2*)(Anext + (size_t)bb * 640 + 512 + seg * 4);
                dst[0] = __floats2half2_rn(v.x, v.y);
                dst[1] = __floats2half2_rn(v.z, v.w);
            }
        }
        asm volatile("bar.sync 1, 128;" ::: "memory");
        mb_wait(sb + OFF_DONE, 0);
        TCFENCE_AFTER();

        const uint32_t tw = tmem + ((uint32_t)wid << 21);
        const float* fr = Fcur + (size_t)b * 512 + nt * 64;
        float* fw = Fnext + (size_t)b * 512 + nt * 64;
        __half* aw = Anext + (size_t)b * 640 + nt * 64;

#pragma unroll
        for (int q = 0; q < 2; ++q) {
            uint32_t a[96], g1[32];
            LDTM32(a,      tw + q * 96);
            LDTM32(a + 32, tw + q * 96 + 32);
            LDTM32(a + 64, tw + q * 96 + 64);
            LDTM32(g1,     tw + 192 + q * 32);
            TCWAIT_LD();
            float hprev[32];
            const float4* hp4 = (const float4*)(fr + q * 32);
#pragma unroll
            for (int i = 0; i < 8; ++i) {
                float4 v = hp4[i];
                hprev[4 * i] = v.x; hprev[4 * i + 1] = v.y;
                hprev[4 * i + 2] = v.z; hprev[4 * i + 3] = v.w;
            }
            float hout[32];
#pragma unroll
            for (int u = 0; u < 32; ++u) {
                int j = q * 32 + u;
                float sr  = __uint_as_float(a[3 * u]);
                float szv = __uint_as_float(a[3 * u + 1]);
                float sn  = __uint_as_float(a[3 * u + 2]);
                float gin = __uint_as_float(g1[u]);
                float r = sigmoidf_(sr + sB[j]);
                float z = sigmoidf_(szv + sB[64 + j]);
                float n = tanhfast(gin + sB[128 + j] + r * ((sn - gin) + sB[192 + j]));
                float h = fmaf(-z, n, n) + z * hprev[u];
                if (t < 511)  // exp(-softplus(x)) == sigmoid(-x)
                    h *= sigmoidf_(-(dtn * sB[256 + j] + sB[320 + j]));
                hout[u] = h;
            }
            float4* fw4 = (float4*)(fw + q * 32);
#pragma unroll
            for (int i = 0; i < 8; ++i)
                fw4[i] = make_float4(hout[4 * i], hout[4 * i + 1], hout[4 * i + 2], hout[4 * i + 3]);
            __half2* aw2 = (__half2*)(aw + q * 32);
#pragma unroll
            for (int i = 0; i < 16; ++i)
                aw2[i] = __floats2half2_rn(hout[2 * i], hout[2 * i + 1]);
        }
    }
    __syncthreads();
    if (wid == 4) TCDEALLOC(tmem, 256);
#endif  // CRU_ARCH_OK
}

// ---------------- head ----------------
__global__ void cru_head_kernel(const float* __restrict__ W_head,
                                const float* __restrict__ b_head,
                                float* __restrict__ out)
{
    __shared__ float sW[8 * 512];
    int tid = threadIdx.x;
    for (int i = tid; i < 4096; i += 128) sW[i] = W_head[i];
    __syncthreads();
    int b = blockIdx.x * 128 + tid;
    const float4* h4 = (const float4*)(g_F0 + (size_t)b * 512);  // t=511 writes F0
    float acc[8];
#pragma unroll
    for (int n = 0; n < 8; n++) acc[n] = 0.f;
    for (int j4 = 0; j4 < 128; ++j4) {
        float4 v = h4[j4];
#pragma unroll
        for (int n = 0; n < 8; n++) {
            acc[n] = fmaf(v.x, sW[n * 512 + 4 * j4],     acc[n]);
            acc[n] = fmaf(v.y, sW[n * 512 + 4 * j4 + 1], acc[n]);
            acc[n] = fmaf(v.z, sW[n * 512 + 4 * j4 + 2], acc[n]);
            acc[n] = fmaf(v.w, sW[n * 512 + 4 * j4 + 3], acc[n]);
        }
    }
#pragma unroll
    for (int n = 0; n < 8; n++) out[b * 8 + n] = acc[n] + b_head[n];
}

// ---------------- host ----------------
typedef CUresult (*EncFn)(CUtensorMap*, CUtensorMapDataType, cuuint32_t, void*,
                          const cuuint64_t*, const cuuint64_t*, const cuuint32_t*,
                          const cuuint32_t*, CUtensorMapInterleave, CUtensorMapSwizzle,
                          CUtensorMapL2promotion, CUtensorMapFloatOOBfill);

static void make_tm2d_f16(EncFn enc, CUtensorMap* tm, void* ptr,
                          uint64_t d0, uint64_t d1, uint32_t b0, uint32_t b1) {
    cuuint64_t dims[2] = {d0, d1};
    cuuint64_t strides[1] = {d0 * 2};
    cuuint32_t box[2] = {b0, b1};
    cuuint32_t es[2] = {1, 1};
    enc(tm, CU_TENSOR_MAP_DATA_TYPE_FLOAT16, 2, ptr, dims, strides, box, es,
        CU_TENSOR_MAP_INTERLEAVE_NONE, CU_TENSOR_MAP_SWIZZLE_128B,
        CU_TENSOR_MAP_L2_PROMOTION_L2_128B, CU_TENSOR_MAP_FLOAT_OOB_FILL_NONE);
}

extern "C" void kernel_launch(void* const* d_in, const int* in_sizes, int n_in,
                              void* d_out, int out_size)
{
    const float* vals   = (const float*)d_in[0];
    const float* maskp  = (const float*)d_in[1];
    const float* ts     = (const float*)d_in[2];
    const float* W_ih   = (const float*)d_in[3];
    const float* W_hh   = (const float*)d_in[4];
    const float* b_ih   = (const float*)d_in[5];
    const float* b_hh   = (const float*)d_in[6];
    const float* W_dec  = (const float*)d_in[7];
    const float* b_dec  = (const float*)d_in[8];
    const float* W_head = (const float*)d_in[9];
    const float* b_head = (const float*)d_in[10];
    float* out = (float*)d_out;

    EncFn enc = nullptr;
    cudaDriverEntryPointQueryResult qr;
    cudaGetDriverEntryPointByVersion("cuTensorMapEncodeTiled", (void**)&enc, 12000,
                                     cudaEnableDefault, &qr);

    void *pA0, *pA1, *pW, *pWn, *pF0, *pF1;
    cudaGetSymbolAddress(&pA0, g_A0);
    cudaGetSymbolAddress(&pA1, g_A1);
    cudaGetSymbolAddress(&pW,  g_W);
    cudaGetSymbolAddress(&pWn, g_Wn);
    cudaGetSymbolAddress(&pF0, g_F0);
    cudaGetSymbolAddress(&pF1, g_F1);

    CUtensorMap tmA0, tmA1, tmW, tmWn;
    make_tm2d_f16(enc, &tmA0, pA0, 640, 2048, 64, 128);
    make_tm2d_f16(enc, &tmA1, pA1, 640, 2048, 64, 128);
    make_tm2d_f16(enc, &tmW,  pW,  640, 1536, 64, 192);
    make_tm2d_f16(enc, &tmWn, pWn, 128, 512,  64, 64);

    cudaFuncSetAttribute(cru_step_kernel,
                         cudaFuncAttributeMaxDynamicSharedMemorySize, SMEM_TOTAL);

    prep_all_kernel<<<6656, 256>>>(vals, maskp, ts, W_ih, W_hh);

    dim3 grid(16, 8);
    for (int t = 0; t < 512; ++t) {
        const float* Fcur = (t & 1) ? (const float*)pF1 : (const float*)pF0;
        float*       Fnxt = (t & 1) ? (float*)pF0 : (float*)pF1;
        __half*      Anxt = (t & 1) ? (__half*)pA0 : (__half*)pA1;
        if (t & 1)
            cru_step_kernel<<<grid, 160, SMEM_TOTAL>>>(tmA1, tmW, tmWn, vals, maskp,
                b_ih, b_hh, W_dec, b_dec, Fcur, Fnxt, Anxt, t);
        else
            cru_step_kernel<<<grid, 160, SMEM_TOTAL>>>(tmA0, tmW, tmWn, vals, maskp,
                b_ih, b_hh, W_dec, b_dec, Fcur, Fnxt, Anxt, t);
    }

    cru_head_kernel<<<16, 128>>>(W_head, b_head, out);
}